// round 9
// baseline (speedup 1.0000x reference)
#include <cuda_runtime.h>

// ---------------- problem constants ----------------
#define S_LEN  512
#define DIN    5
#define HID    128
#define GATES  512
#define NBLK   128     // recurrence blocks, each owns BPB batch rows
#define BPB    8
#define NG     32      // k-groups (of 4) per 128-wide K
#define NSM    23      // k-groups cached in smem (rest in registers)
#define NTH    384     // phase threads = 128 j x 3 kh

// phase smem layout (float offsets)
#define OFF_WC  0
#define OFF_HA  (NSM*GATES*4)            // 47104 : hA [4b][128j]
#define OFF_HB  (OFF_HA + 512)           // 47616 : hB
#define OFF_XP  (OFF_HB + 512)           // 48128 : [2 half][2 slot][4 r][128 j][4 q]
#define PH_SMEM_BYTES ((OFF_XP + 8192)*4)   // 225280

// gemm smem: Ws [32 g][64 c][4k] = 8192 floats + Ht 2 x 4096 (4 t x 8 b x 128 j)
#define GM_THREADS 256
#define GM_HT_OFF  (NG*64*4)             // 8192 floats
#define GM_SMEM_BYTES ((GM_HT_OFF + 2*4096)*4)   // 65536 -> 3 CTAs/SM

// ---------------- global scratch (static) ----------------
__device__ __align__(16) float g_P1[NG * GATES * 4];   // packed w_hh0
__device__ __align__(16) float g_P2[NG * GATES * 4];   // packed w_hh1
__device__ __align__(16) float g_P3[NG * GATES * 4];   // packed w_ih1
__device__ __align__(16) float g_h1 [(size_t)NBLK * S_LEN * BPB * HID];    // [blk][t][b][j]
__device__ __align__(16) float g_xg1[(size_t)NBLK * S_LEN * GATES * BPB];  // [blk][t][col][b]

// ---------------- helpers ----------------
typedef unsigned long long u64;
__device__ __forceinline__ void ffma2(u64 &d, u64 a, u64 b) {
    asm("fma.rn.f32x2 %0, %1, %2, %0;" : "+l"(d) : "l"(a), "l"(b));
}
__device__ __forceinline__ float flo(u64 v) { return __uint_as_float((unsigned)v); }
__device__ __forceinline__ float fhi(u64 v) { return __uint_as_float((unsigned)(v >> 32)); }
__device__ __forceinline__ float sigf(float x) {
    return __fdividef(1.0f, 1.0f + __expf(-x));
}
__device__ __forceinline__ float tanhf_fast(float x) {
    float e = __expf(2.0f * x);
    return 1.0f - __fdividef(2.0f, e + 1.0f);
}

// smem-group accumulation over 4 batch rows
template<int G0, int G1>
__device__ __forceinline__ void accum_smem(u64 (&acc)[4][4],
                                           const ulonglong2* __restrict__ W,
                                           const ulonglong2* __restrict__ H,
                                           int j) {
#pragma unroll
    for (int g = G0; g < G1; g++) {
        ulonglong2 w[4];
#pragma unroll
        for (int q = 0; q < 4; q++) w[q] = W[g * GATES + q * HID + j];
#pragma unroll
        for (int b = 0; b < 4; b++) {
            ulonglong2 hv = H[b * 32 + g];
#pragma unroll
            for (int q = 0; q < 4; q++) {
                ffma2(acc[q][b], w[q].x, hv.x);
                ffma2(acc[q][b], w[q].y, hv.y);
            }
        }
    }
}

// ---------------- K1: pack weights ----------------
__global__ void pack_kernel(const float* __restrict__ whh0,
                            const float* __restrict__ whh1,
                            const float* __restrict__ wih1) {
    int i = blockIdx.x * blockDim.x + threadIdx.x;
    if (i >= GATES * HID) return;
    int col = i / HID, k = i % HID;
    int g = k >> 2, dk = k & 3;
    size_t o = ((size_t)g * GATES + col) * 4 + dk;
    g_P1[o] = whh0[col * HID + k];
    g_P2[o] = whh1[col * HID + k];
    g_P3[o] = wih1[col * HID + k];
}

// ---------------- K3: xg1 = h1 @ w_ih1^T + biases ----------------
// grid (8 ch, NBLK, 2 th), 256 thr, 3 CTAs/SM.
// CTA: 64 cols x 256 timesteps, tiles of 4 t.
// thread: cp = tid&31 -> 2 cols; rw = tid>>5 in 0..7: tt4 = rw>>1 (t in tile),
//         bh = rw&1 -> batch rows bh*4..bh*4+3.
__global__ void __launch_bounds__(GM_THREADS, 3) xg1_gemm(const float* __restrict__ bih1,
                                                          const float* __restrict__ bhh1) {
    extern __shared__ float sm[];
    float4* Ws4 = (float4*)sm;
    float*  Ht  = sm + GM_HT_OFF;

    const int tid = threadIdx.x;
    const int ch  = blockIdx.x, blk = blockIdx.y, th = blockIdx.z;
    const int cp  = tid & 31;
    const int rw  = tid >> 5;
    const int t4  = rw >> 1;                  // t within 4-t tile
    const int bh  = rw & 1;                   // batch half: rows bh*4..+3
    const int c0  = ch * 64 + cp * 2;
    const int t0  = th * (S_LEN / 2);         // 256 t per CTA

    // weight slice: 32 g x 64 cols
    {
        const float4* P34 = (const float4*)g_P3;
        for (int i = tid; i < NG * 64; i += GM_THREADS) {
            int g = i >> 6, c = i & 63;
            Ws4[i] = __ldg(&P34[g * GATES + ch * 64 + c]);
        }
    }
    const float bs0 = __ldg(bih1 + c0)     + __ldg(bhh1 + c0);
    const float bs1 = __ldg(bih1 + c0 + 1) + __ldg(bhh1 + c0 + 1);

    // preload tile 0 (4 t x 8 b x 128 j = 1024 float4)
    {
        const float4* hsrc = (const float4*)(g_h1 + (size_t)(blk * S_LEN + t0) * (BPB * HID));
#pragma unroll
        for (int k = 0; k < 4; k++)
            ((float4*)Ht)[tid + 256 * k] = __ldg(hsrc + tid + 256 * k);
    }
    __syncthreads();

    const ulonglong2* WsD = (const ulonglong2*)sm;
    int pb = 0;
    for (int tt = 0; tt < 64; tt++) {                 // 64 tiles of 4 t
        const int tg = t0 + tt * 4 + t4;              // my global t
        const bool has = (tt + 1 < 64);
        float4 pre[4];
        if (has) {
            const float4* hsrc = (const float4*)(g_h1 +
                (size_t)(blk * S_LEN + t0 + (tt + 1) * 4) * (BPB * HID));
#pragma unroll
            for (int k = 0; k < 4; k++) pre[k] = __ldg(hsrc + tid + 256 * k);
        }

        const ulonglong2* HtD = (const ulonglong2*)(Ht + pb * 4096);
        u64 a0[4] = {0,0,0,0}, a1[4] = {0,0,0,0};
#pragma unroll 8
        for (int g = 0; g < NG; g++) {
            ulonglong2 w0 = WsD[g * 64 + cp * 2];
            ulonglong2 w1 = WsD[g * 64 + cp * 2 + 1];
#pragma unroll
            for (int r = 0; r < 4; r++) {
                ulonglong2 hv = HtD[(t4 * 8 + bh * 4 + r) * 32 + g];
                ffma2(a0[r], w0.x, hv.x); ffma2(a0[r], w0.y, hv.y);
                ffma2(a1[r], w1.x, hv.x); ffma2(a1[r], w1.y, hv.y);
            }
        }
        float4 o0 = make_float4(flo(a0[0]) + fhi(a0[0]) + bs0,
                                flo(a0[1]) + fhi(a0[1]) + bs0,
                                flo(a0[2]) + fhi(a0[2]) + bs0,
                                flo(a0[3]) + fhi(a0[3]) + bs0);
        float4 o1 = make_float4(flo(a1[0]) + fhi(a1[0]) + bs1,
                                flo(a1[1]) + fhi(a1[1]) + bs1,
                                flo(a1[2]) + fhi(a1[2]) + bs1,
                                flo(a1[3]) + fhi(a1[3]) + bs1);
        size_t base = ((size_t)(blk * S_LEN + tg) * GATES + c0) * BPB + bh * 4;
        *(float4*)(g_xg1 + base)       = o0;
        *(float4*)(g_xg1 + base + BPB) = o1;

        if (has) {
#pragma unroll
            for (int k = 0; k < 4; k++)
                ((float4*)(Ht + (pb ^ 1) * 4096))[tid + 256 * k] = pre[k];
        }
        __syncthreads();
        pb ^= 1;
    }
}

// ---------------- K2/K4: recurrent phases, batch-half pipelined ----------------
// 384 thr = 128 j x 3 kh. Half A = rows 0-3, half B = rows 4-7.
// alpha: GEMM_A(t) + finalize_B(t-1). beta: GEMM_B(t) + finalize_A(t).
template<int PHASE>
__global__ void __launch_bounds__(NTH, 1) lstm_phase(
    const float* __restrict__ x,
    const float* __restrict__ wih0,
    const float* __restrict__ bih,
    const float* __restrict__ bhh,
    const float* __restrict__ fcw,
    const float* __restrict__ fcb,
    float* __restrict__ out)
{
    extern __shared__ float sm[];
    const float* Pg = (PHASE == 1) ? g_P1 : g_P2;

    const int tid = threadIdx.x;
    const int j   = tid & (HID - 1);
    const int kh  = tid >> 7;
    const int blk = blockIdx.x;
    const int bg0 = blk * BPB;
    const int gb  = NSM + kh * 3;

    // register-resident weight groups
    ulonglong2 wr[3][4];
    {
        const ulonglong2* PgD = (const ulonglong2*)Pg;
#pragma unroll
        for (int s = 0; s < 3; s++)
#pragma unroll
            for (int q = 0; q < 4; q++)
                wr[s][q] = __ldg(&PgD[(gb + s) * GATES + q * HID + j]);
    }

    // finalizer constants (phase1 only; phase2 biases live in xg1)
    float bias[4], wihr[4][DIN];
    if (PHASE == 1 && kh < 2) {
#pragma unroll
        for (int q = 0; q < 4; q++) {
            int r = q * HID + j;
            bias[q] = __ldg(bih + r) + __ldg(bhh + r);
#pragma unroll
            for (int d = 0; d < DIN; d++) wihr[q][d] = __ldg(wih0 + r * DIN + d);
        }
    }

    // load smem weights; zero h buffers
    {
        const float4* src = (const float4*)Pg;
        float4*       dst = (float4*)(sm + OFF_WC);
        for (int i = tid; i < NSM * GATES; i += NTH) dst[i] = __ldg(src + i);
    }
    for (int i = tid; i < 1024; i += NTH) sm[OFF_HA + i] = 0.f;
    __syncthreads();

    const ulonglong2* WcD = (const ulonglong2*)(sm + OFF_WC);

    float c[2][2] = {{0.f, 0.f}, {0.f, 0.f}};       // [half][row]
    float prB[4][2];                                 // own B partials held across barrier
    float2 xqA[4], xqB[4];                           // phase2 inputs
    float  xvA[2][DIN], xvB[2][DIN];                 // phase1 inputs

    // gemm over one half + export (vectorized) + own-save
    auto gemm_half = [&](int hoff, int half, float (&prOwn)[4][2]) {
        const ulonglong2* H = (const ulonglong2*)(sm + hoff);
        u64 acc[4][4];
#pragma unroll
        for (int q = 0; q < 4; q++)
#pragma unroll
            for (int b = 0; b < 4; b++) acc[q][b] = 0ull;
        if (kh == 0)      accum_smem<0,  7 >(acc, WcD, H, j);
        else if (kh == 1) accum_smem<7,  14>(acc, WcD, H, j);
        else              accum_smem<14, NSM>(acc, WcD, H, j);
#pragma unroll
        for (int s = 0; s < 3; s++) {
#pragma unroll
            for (int b = 0; b < 4; b++) {
                ulonglong2 hv = H[b * 32 + gb + s];
#pragma unroll
                for (int q = 0; q < 4; q++) {
                    ffma2(acc[q][b], wr[s][q].x, hv.x);
                    ffma2(acc[q][b], wr[s][q].y, hv.y);
                }
            }
        }
        float pr[4][4];
#pragma unroll
        for (int q = 0; q < 4; q++)
#pragma unroll
            for (int b = 0; b < 4; b++) pr[q][b] = flo(acc[q][b]) + fhi(acc[q][b]);

        // XP layout: [half][slot][r][j][q]  -> float4 stores over q
        float* XP = sm + OFF_XP + half * 4096;
        if (kh == 0) {
#pragma unroll
            for (int r = 2; r < 4; r++)
                *(float4*)(XP + r * 512 + j * 4) =
                    make_float4(pr[0][r], pr[1][r], pr[2][r], pr[3][r]);
#pragma unroll
            for (int q = 0; q < 4; q++) { prOwn[q][0] = pr[q][0]; prOwn[q][1] = pr[q][1]; }
        } else if (kh == 1) {
#pragma unroll
            for (int r = 0; r < 2; r++)
                *(float4*)(XP + r * 512 + j * 4) =
                    make_float4(pr[0][r], pr[1][r], pr[2][r], pr[3][r]);
#pragma unroll
            for (int q = 0; q < 4; q++) { prOwn[q][0] = pr[q][2]; prOwn[q][1] = pr[q][3]; }
        } else {
#pragma unroll
            for (int r = 0; r < 4; r++)
                *(float4*)(XP + 2048 + r * 512 + j * 4) =
                    make_float4(pr[0][r], pr[1][r], pr[2][r], pr[3][r]);
        }
    };

    // finalize 2 rows of a half (kh<2 only)
    auto finalize_half = [&](int hoff, int half, int t, float (&prOwn)[4][2],
                             float2 (&xq)[4], float (&xv)[2][DIN]) {
        const float* XP = sm + OFF_XP + half * 4096;
#pragma unroll
        for (int r2 = 0; r2 < 2; r2++) {
            int rloc = 2 * kh + r2;
            float4 p0 = *(const float4*)(XP + rloc * 512 + j * 4);
            float4 p1 = *(const float4*)(XP + 2048 + rloc * 512 + j * 4);
            float gate[4];
            gate[0] = prOwn[0][r2] + p0.x + p1.x;
            gate[1] = prOwn[1][r2] + p0.y + p1.y;
            gate[2] = prOwn[2][r2] + p0.z + p1.z;
            gate[3] = prOwn[3][r2] + p0.w + p1.w;
            if (PHASE == 1) {
#pragma unroll
                for (int q = 0; q < 4; q++) {
                    float s = bias[q];
#pragma unroll
                    for (int d = 0; d < DIN; d++) s = fmaf(wihr[q][d], xv[r2][d], s);
                    gate[q] += s;
                }
            } else {
                gate[0] += (r2 == 0 ? xq[0].x : xq[0].y);
                gate[1] += (r2 == 0 ? xq[1].x : xq[1].y);
                gate[2] += (r2 == 0 ? xq[2].x : xq[2].y);
                gate[3] += (r2 == 0 ? xq[3].x : xq[3].y);
            }
            float cc = sigf(gate[1]) * c[half][r2] + sigf(gate[0]) * tanhf_fast(gate[2]);
            c[half][r2] = cc;
            float h = sigf(gate[3]) * tanhf_fast(cc);
            sm[hoff + rloc * HID + j] = h;
            if (PHASE == 1)
                g_h1[((size_t)(blk * S_LEN + t) * BPB + half * 4 + rloc) * HID + j] = h;
        }
    };

    auto load_inputs = [&](int half, int t, float2 (&xq)[4], float (&xv)[2][DIN]) {
        if (kh >= 2) return;
        if (PHASE == 2) {
            const float* xp = g_xg1 + (size_t)(blk * S_LEN + t) * (GATES * BPB);
#pragma unroll
            for (int q = 0; q < 4; q++)
                xq[q] = __ldg((const float2*)(xp + (q * HID + j) * BPB + half * 4 + 2 * kh));
        } else {
#pragma unroll
            for (int r2 = 0; r2 < 2; r2++) {
                int b = half * 4 + 2 * kh + r2;
                const float* xr = x + ((size_t)(bg0 + b) * S_LEN + t) * DIN;
#pragma unroll
                for (int d = 0; d < DIN; d++) xv[r2][d] = __ldg(xr + d);
            }
        }
    };

    for (int t = 0; t < S_LEN; t++) {
        // ---- alpha: GEMM_A(t) + finalize_B(t-1) ----
        load_inputs(0, t, xqA, xvA);
        if (t > 0 && kh < 2) finalize_half(OFF_HB, 1, t - 1, prB, xqB, xvB);
        {
            float prA[4][2];
            gemm_half(OFF_HA, 0, prA);
            __syncthreads();
            // ---- beta: GEMM_B(t) + finalize_A(t) ----
            load_inputs(1, t, xqB, xvB);
            if (kh < 2) finalize_half(OFF_HA, 0, t, prA, xqA, xvA);
        }
        gemm_half(OFF_HB, 1, prB);
        __syncthreads();
    }
    // drain: finalize_B(511)
    if (kh < 2) finalize_half(OFF_HB, 1, S_LEN - 1, prB, xqB, xvB);
    __syncthreads();

    if (PHASE == 2 && tid < 256) {
        int w = tid >> 5, lane = tid & 31;
        const float* hrow = sm + (w < 4 ? OFF_HA + w * HID : OFF_HB + (w - 4) * HID);
        float s = 0.f;
#pragma unroll
        for (int m = 0; m < HID; m += 32)
            s += hrow[lane + m] * __ldg(fcw + lane + m);
#pragma unroll
        for (int o = 16; o > 0; o >>= 1) s += __shfl_down_sync(0xffffffffu, s, o);
        if (lane == 0) out[bg0 + w] = s + __ldg(fcb);
    }
}

// ---------------- launch ----------------
extern "C" void kernel_launch(void* const* d_in, const int* in_sizes, int n_in,
                              void* d_out, int out_size) {
    const float* x    = (const float*)d_in[0];
    const float* wih0 = (const float*)d_in[1];
    const float* whh0 = (const float*)d_in[2];
    const float* bih0 = (const float*)d_in[3];
    const float* bhh0 = (const float*)d_in[4];
    const float* wih1 = (const float*)d_in[5];
    const float* whh1 = (const float*)d_in[6];
    const float* bih1 = (const float*)d_in[7];
    const float* bhh1 = (const float*)d_in[8];
    const float* fcw  = (const float*)d_in[9];
    const float* fcb  = (const float*)d_in[10];
    float* out = (float*)d_out;
    (void)in_sizes; (void)n_in; (void)out_size;

    cudaFuncSetAttribute(lstm_phase<1>, cudaFuncAttributeMaxDynamicSharedMemorySize, PH_SMEM_BYTES);
    cudaFuncSetAttribute(lstm_phase<2>, cudaFuncAttributeMaxDynamicSharedMemorySize, PH_SMEM_BYTES);
    cudaFuncSetAttribute(xg1_gemm,      cudaFuncAttributeMaxDynamicSharedMemorySize, GM_SMEM_BYTES);

    pack_kernel<<<(GATES * HID + 255) / 256, 256>>>(whh0, whh1, wih1);
    lstm_phase<1><<<NBLK, NTH, PH_SMEM_BYTES>>>(x, wih0, bih0, bhh0, fcw, fcb, out);
    xg1_gemm<<<dim3(8, NBLK, 2), GM_THREADS, GM_SMEM_BYTES>>>(bih1, bhh1);
    lstm_phase<2><<<NBLK, NTH, PH_SMEM_BYTES>>>(x, wih0, bih1, bhh1, fcw, fcb, out);
}

// round 10
// speedup vs baseline: 1.1097x; 1.1097x over previous
#include <cuda_runtime.h>

// ---------------- problem constants ----------------
#define S_LEN  512
#define DIN    5
#define HID    128
#define GATES  512
#define BATCH  1024
#define NBLK   147     // recurrence blocks: 146 x 7 rows + 1 x 2 rows
#define RPB    7       // rows per block (logical)
#define BST    8       // row stride in g_h1 / g_xg1 (padded)
#define NG     32      // k-groups (of 4) per 128-wide K
#define NSM    23      // k-groups cached in smem (rest in registers)
#define NTH    384     // phase threads = 128 j x 3 kh

// phase smem layout (float offsets)
#define OFF_WC  0
#define OFF_HA  (NSM*GATES*4)            // 47104 : hA [4][128]
#define OFF_HB  (OFF_HA + 512)           // 47616 : hB [3][128] (512 reserved)
#define OFF_XP  (OFF_HB + 512)           // 48128 : [2 half][2 slot][4 r][128 j][4 q]
#define PH_SMEM_BYTES ((OFF_XP + 8192)*4)   // 225280

// gemm smem: Ws [32 g][256 c][4k] + Ht 2 x 4096 (4 t x 8 b x 128 j)
#define GM_THREADS 512
#define GM_HT_OFF  (NG*256*4)            // 32768 floats
#define GM_SMEM_BYTES ((GM_HT_OFF + 2*4096)*4)   // 163840

// ---------------- global scratch (static) ----------------
__device__ __align__(16) float g_P1[NG * GATES * 4];   // packed w_hh0
__device__ __align__(16) float g_P2[NG * GATES * 4];   // packed w_hh1
__device__ __align__(16) float g_P3[NG * GATES * 4];   // packed w_ih1
__device__ __align__(16) float g_h1 [(size_t)NBLK * S_LEN * BST * HID];    // [blk][t][b8][j]
__device__ __align__(16) float g_xg1[(size_t)NBLK * S_LEN * GATES * BST];  // [blk][t][col][b8]

// ---------------- helpers ----------------
typedef unsigned long long u64;
__device__ __forceinline__ void ffma2(u64 &d, u64 a, u64 b) {
    asm("fma.rn.f32x2 %0, %1, %2, %0;" : "+l"(d) : "l"(a), "l"(b));
}
__device__ __forceinline__ float flo(u64 v) { return __uint_as_float((unsigned)v); }
__device__ __forceinline__ float fhi(u64 v) { return __uint_as_float((unsigned)(v >> 32)); }
__device__ __forceinline__ float sigf(float x) {
    return __fdividef(1.0f, 1.0f + __expf(-x));
}
__device__ __forceinline__ float tanhf_fast(float x) {
    float e = __expf(2.0f * x);
    return 1.0f - __fdividef(2.0f, e + 1.0f);
}

// smem-group accumulation over NB batch rows
template<int G0, int G1, int NB>
__device__ __forceinline__ void accum_smem(u64 (&acc)[4][NB],
                                           const ulonglong2* __restrict__ W,
                                           const ulonglong2* __restrict__ H,
                                           int j) {
#pragma unroll
    for (int g = G0; g < G1; g++) {
        ulonglong2 w[4];
#pragma unroll
        for (int q = 0; q < 4; q++) w[q] = W[g * GATES + q * HID + j];
#pragma unroll
        for (int b = 0; b < NB; b++) {
            ulonglong2 hv = H[b * 32 + g];
#pragma unroll
            for (int q = 0; q < 4; q++) {
                ffma2(acc[q][b], w[q].x, hv.x);
                ffma2(acc[q][b], w[q].y, hv.y);
            }
        }
    }
}

template<int NB>
__device__ __forceinline__ void gemm_body(int kh, const ulonglong2* __restrict__ WcD,
                                          const ulonglong2 (&wr)[3][4], int gb,
                                          const ulonglong2* __restrict__ H, int j,
                                          float (&pr)[4][NB]) {
    u64 acc[4][NB];
#pragma unroll
    for (int q = 0; q < 4; q++)
#pragma unroll
        for (int b = 0; b < NB; b++) acc[q][b] = 0ull;
    if (kh == 0)      accum_smem<0,  7,  NB>(acc, WcD, H, j);
    else if (kh == 1) accum_smem<7,  14, NB>(acc, WcD, H, j);
    else              accum_smem<14, NSM, NB>(acc, WcD, H, j);
#pragma unroll
    for (int s = 0; s < 3; s++) {
#pragma unroll
        for (int b = 0; b < NB; b++) {
            ulonglong2 hv = H[b * 32 + gb + s];
#pragma unroll
            for (int q = 0; q < 4; q++) {
                ffma2(acc[q][b], wr[s][q].x, hv.x);
                ffma2(acc[q][b], wr[s][q].y, hv.y);
            }
        }
    }
#pragma unroll
    for (int q = 0; q < 4; q++)
#pragma unroll
        for (int b = 0; b < NB; b++) pr[q][b] = flo(acc[q][b]) + fhi(acc[q][b]);
}

// ---------------- K1: pack weights ----------------
__global__ void pack_kernel(const float* __restrict__ whh0,
                            const float* __restrict__ whh1,
                            const float* __restrict__ wih1) {
    int i = blockIdx.x * blockDim.x + threadIdx.x;
    if (i >= GATES * HID) return;
    int col = i / HID, k = i % HID;
    int g = k >> 2, dk = k & 3;
    size_t o = ((size_t)g * GATES + col) * 4 + dk;
    g_P1[o] = whh0[col * HID + k];
    g_P2[o] = whh1[col * HID + k];
    g_P3[o] = wih1[col * HID + k];
}

// ---------------- K3: xg1 = h1 @ w_ih1^T + biases ----------------
// grid (2 ch, NBLK, 4 tq), 512 thr. thread: cp=tid&127 -> 2 cols, rw=tid>>7 -> 1 t of 4-t tile, 7 b.
__global__ void __launch_bounds__(GM_THREADS, 1) xg1_gemm(const float* __restrict__ bih1,
                                                          const float* __restrict__ bhh1) {
    extern __shared__ float sm[];
    float4* Ws4 = (float4*)sm;
    float*  Ht  = sm + GM_HT_OFF;

    const int tid = threadIdx.x;
    const int ch  = blockIdx.x, blk = blockIdx.y, tq = blockIdx.z;
    const int cp  = tid & 127;
    const int rw  = tid >> 7;                 // 0..3
    const int c0  = ch * 256 + cp * 2;
    const int t0  = tq * (S_LEN / 4);         // 128 t per CTA

    {
        const float4* P34 = (const float4*)g_P3;
        for (int i = tid; i < NG * 256; i += GM_THREADS) {
            int g = i >> 8, c = i & 255;
            Ws4[i] = __ldg(&P34[g * GATES + ch * 256 + c]);
        }
    }
    const float bs0 = __ldg(bih1 + c0)     + __ldg(bhh1 + c0);
    const float bs1 = __ldg(bih1 + c0 + 1) + __ldg(bhh1 + c0 + 1);

    {
        const float4* hsrc = (const float4*)(g_h1 + (size_t)(blk * S_LEN + t0) * (BST * HID));
        ((float4*)Ht)[tid * 2]     = __ldg(hsrc + tid * 2);
        ((float4*)Ht)[tid * 2 + 1] = __ldg(hsrc + tid * 2 + 1);
    }
    __syncthreads();

    const ulonglong2* WsD = (const ulonglong2*)sm;
    int pb = 0;
    for (int tt = 0; tt < 32; tt++) {
        const int t = t0 + tt * 4 + rw;
        const bool has = (tt + 1 < 32);
        float4 pre0, pre1;
        if (has) {
            const float4* hsrc = (const float4*)(g_h1 +
                (size_t)(blk * S_LEN + t0 + (tt + 1) * 4) * (BST * HID));
            pre0 = __ldg(hsrc + tid * 2);
            pre1 = __ldg(hsrc + tid * 2 + 1);
        }

        const ulonglong2* HtD = (const ulonglong2*)(Ht + pb * 4096);
        u64 a0[RPB] = {0,0,0,0,0,0,0}, a1[RPB] = {0,0,0,0,0,0,0};
#pragma unroll 8
        for (int g = 0; g < NG; g++) {
            ulonglong2 w0 = WsD[g * 256 + cp * 2];
            ulonglong2 w1 = WsD[g * 256 + cp * 2 + 1];
#pragma unroll
            for (int b = 0; b < RPB; b++) {
                ulonglong2 hv = HtD[(rw * BST + b) * 32 + g];
                ffma2(a0[b], w0.x, hv.x); ffma2(a0[b], w0.y, hv.y);
                ffma2(a1[b], w1.x, hv.x); ffma2(a1[b], w1.y, hv.y);
            }
        }
        float o0[BST], o1[BST];
#pragma unroll
        for (int b = 0; b < RPB; b++) {
            o0[b] = flo(a0[b]) + fhi(a0[b]) + bs0;
            o1[b] = flo(a1[b]) + fhi(a1[b]) + bs1;
        }
        o0[7] = 0.f; o1[7] = 0.f;
        float4* dst = (float4*)(g_xg1 + ((size_t)(blk * S_LEN + t) * GATES + c0) * BST);
        dst[0] = make_float4(o0[0], o0[1], o0[2], o0[3]);
        dst[1] = make_float4(o0[4], o0[5], o0[6], o0[7]);
        dst[2] = make_float4(o1[0], o1[1], o1[2], o1[3]);
        dst[3] = make_float4(o1[4], o1[5], o1[6], o1[7]);

        if (has) {
            ((float4*)(Ht + (pb ^ 1) * 4096))[tid * 2]     = pre0;
            ((float4*)(Ht + (pb ^ 1) * 4096))[tid * 2 + 1] = pre1;
        }
        __syncthreads();
        pb ^= 1;
    }
}

// ---------------- K2/K4: recurrent phases, batch-half pipelined, 7 rows/block ----
// Half A = local rows 0-3 (4), half B = local rows 4-6 (3).
// alpha: GEMM_A(t) + finalize_B(t-1). beta: GEMM_B(t) + finalize_A(t).
// kh0: smem g0-6 + reg g23-25; kh1: g7-13 + g26-28; kh2: g14-22 + g29-31.
// finalize A: kh0 -> r0,1 ; kh1 -> r2,3. finalize B: kh0 -> r0,1 ; kh1 -> r2.
template<int PHASE>
__global__ void __launch_bounds__(NTH, 1) lstm_phase(
    const float* __restrict__ x,
    const float* __restrict__ wih0,
    const float* __restrict__ bih,
    const float* __restrict__ bhh,
    const float* __restrict__ fcw,
    const float* __restrict__ fcb,
    float* __restrict__ out)
{
    extern __shared__ float sm[];
    const float* Pg = (PHASE == 1) ? g_P1 : g_P2;

    const int tid = threadIdx.x;
    const int j   = tid & (HID - 1);
    const int kh  = tid >> 7;
    const int blk = blockIdx.x;
    const int bg0 = blk * RPB;
    const int valid = (BATCH - bg0 < RPB) ? (BATCH - bg0) : RPB;
    const int gb  = NSM + kh * 3;

    ulonglong2 wr[3][4];
    {
        const ulonglong2* PgD = (const ulonglong2*)Pg;
#pragma unroll
        for (int s = 0; s < 3; s++)
#pragma unroll
            for (int q = 0; q < 4; q++)
                wr[s][q] = __ldg(&PgD[(gb + s) * GATES + q * HID + j]);
    }

    float bias[4], wihr[4][DIN];
    if (PHASE == 1 && kh < 2) {
#pragma unroll
        for (int q = 0; q < 4; q++) {
            int r = q * HID + j;
            bias[q] = __ldg(bih + r) + __ldg(bhh + r);
#pragma unroll
            for (int d = 0; d < DIN; d++) wihr[q][d] = __ldg(wih0 + r * DIN + d);
        }
    }

    {
        const float4* src = (const float4*)Pg;
        float4*       dst = (float4*)(sm + OFF_WC);
        for (int i = tid; i < NSM * GATES; i += NTH) dst[i] = __ldg(src + i);
    }
    for (int i = tid; i < 1024; i += NTH) sm[OFF_HA + i] = 0.f;
    __syncthreads();

    const ulonglong2* WcD = (const ulonglong2*)(sm + OFF_WC);

    float c[2][2] = {{0.f, 0.f}, {0.f, 0.f}};
    float prB[4][3];
    float2 xqA[4], xqB[4];
    float  xvA[2][DIN], xvB[2][DIN];

    // -------- export helpers --------
    auto exportA = [&](float (&pr)[4][4], float (&prOwn)[4][2]) {
        float* XP = sm + OFF_XP;               // half A
        if (kh == 0) {
#pragma unroll
            for (int r = 2; r < 4; r++)
                *(float4*)(XP + r * 512 + j * 4) =
                    make_float4(pr[0][r], pr[1][r], pr[2][r], pr[3][r]);
#pragma unroll
            for (int q = 0; q < 4; q++) { prOwn[q][0] = pr[q][0]; prOwn[q][1] = pr[q][1]; }
        } else if (kh == 1) {
#pragma unroll
            for (int r = 0; r < 2; r++)
                *(float4*)(XP + r * 512 + j * 4) =
                    make_float4(pr[0][r], pr[1][r], pr[2][r], pr[3][r]);
#pragma unroll
            for (int q = 0; q < 4; q++) { prOwn[q][0] = pr[q][2]; prOwn[q][1] = pr[q][3]; }
        } else {
#pragma unroll
            for (int r = 0; r < 4; r++)
                *(float4*)(XP + 2048 + r * 512 + j * 4) =
                    make_float4(pr[0][r], pr[1][r], pr[2][r], pr[3][r]);
        }
    };
    auto exportB = [&](float (&pr)[4][3], float (&prOwn)[4][3]) {
        float* XP = sm + OFF_XP + 4096;        // half B
        if (kh == 0) {
            *(float4*)(XP + 2 * 512 + j * 4) =
                make_float4(pr[0][2], pr[1][2], pr[2][2], pr[3][2]);
#pragma unroll
            for (int q = 0; q < 4; q++) { prOwn[q][0] = pr[q][0]; prOwn[q][1] = pr[q][1]; }
        } else if (kh == 1) {
#pragma unroll
            for (int r = 0; r < 2; r++)
                *(float4*)(XP + r * 512 + j * 4) =
                    make_float4(pr[0][r], pr[1][r], pr[2][r], pr[3][r]);
#pragma unroll
            for (int q = 0; q < 4; q++) prOwn[q][0] = pr[q][2];
        } else {
#pragma unroll
            for (int r = 0; r < 3; r++)
                *(float4*)(XP + 2048 + r * 512 + j * 4) =
                    make_float4(pr[0][r], pr[1][r], pr[2][r], pr[3][r]);
        }
    };

    // finalize rows of one half. half: 0=A(rows 0-3), 1=B(rows 4-6).
    auto finalize_half = [&](int hoff, int half, int t, const float* prOwn0, const float* prOwn1,
                             float2 (&xq)[4], float (&xv)[2][DIN]) {
        const float* XP = sm + OFF_XP + half * 4096;
        const int nown = (kh == 0) ? 2 : (half == 0 ? 2 : 1);
#pragma unroll
        for (int r2 = 0; r2 < 2; r2++) {
            if (r2 >= nown) break;
            int rloc = 2 * kh + r2;
            const float* po = (r2 == 0) ? prOwn0 : prOwn1;
            float4 p0 = *(const float4*)(XP + rloc * 512 + j * 4);
            float4 p1 = *(const float4*)(XP + 2048 + rloc * 512 + j * 4);
            float gate[4];
            gate[0] = po[0] + p0.x + p1.x;
            gate[1] = po[1] + p0.y + p1.y;
            gate[2] = po[2] + p0.z + p1.z;
            gate[3] = po[3] + p0.w + p1.w;
            if (PHASE == 1) {
#pragma unroll
                for (int q = 0; q < 4; q++) {
                    float s = bias[q];
#pragma unroll
                    for (int d = 0; d < DIN; d++) s = fmaf(wihr[q][d], xv[r2][d], s);
                    gate[q] += s;
                }
            } else {
                gate[0] += (r2 == 0 ? xq[0].x : xq[0].y);
                gate[1] += (r2 == 0 ? xq[1].x : xq[1].y);
                gate[2] += (r2 == 0 ? xq[2].x : xq[2].y);
                gate[3] += (r2 == 0 ? xq[3].x : xq[3].y);
            }
            float cc = sigf(gate[1]) * c[half][r2] + sigf(gate[0]) * tanhf_fast(gate[2]);
            c[half][r2] = cc;
            float h = sigf(gate[3]) * tanhf_fast(cc);
            sm[hoff + rloc * HID + j] = h;
            if (PHASE == 1)
                g_h1[((size_t)(blk * S_LEN + t) * BST + half * 4 + rloc) * HID + j] = h;
        }
    };

    auto load_inputs = [&](int half, int t, float2 (&xq)[4], float (&xv)[2][DIN]) {
        if (kh >= 2) return;
        if (PHASE == 2) {
            const float* xp = g_xg1 + (size_t)(blk * S_LEN + t) * (GATES * BST);
            int off = half * 4 + 2 * kh;
#pragma unroll
            for (int q = 0; q < 4; q++)
                xq[q] = __ldg((const float2*)(xp + (q * HID + j) * BST + off));
        } else {
#pragma unroll
            for (int r2 = 0; r2 < 2; r2++) {
                int gr = bg0 + half * 4 + 2 * kh + r2;
                if (gr > BATCH - 1) gr = BATCH - 1;
                const float* xr = x + ((size_t)gr * S_LEN + t) * DIN;
#pragma unroll
                for (int d = 0; d < DIN; d++) xv[r2][d] = __ldg(xr + d);
            }
        }
    };

    float prOwnA[4][2];
    float prOwnBv[4][3];   // [q][0..1] used as own (kh0: 2 rows, kh1: 1 row)

    for (int t = 0; t < S_LEN; t++) {
        // ---- alpha: GEMM_A(t) + finalize_B(t-1) ----
        load_inputs(0, t, xqA, xvA);
        if (t > 0 && kh < 2) {
            float o0[4] = {prOwnBv[0][0], prOwnBv[1][0], prOwnBv[2][0], prOwnBv[3][0]};
            float o1[4] = {prOwnBv[0][1], prOwnBv[1][1], prOwnBv[2][1], prOwnBv[3][1]};
            finalize_half(OFF_HB, 1, t - 1, o0, o1, xqB, xvB);
        }
        {
            float prA[4][4];
            gemm_body<4>(kh, WcD, wr, gb, (const ulonglong2*)(sm + OFF_HA), j, prA);
            exportA(prA, prOwnA);
            __syncthreads();
            // ---- beta: GEMM_B(t) + finalize_A(t) ----
            load_inputs(1, t, xqB, xvB);
            if (kh < 2) {
                float o0[4] = {prOwnA[0][0], prOwnA[1][0], prOwnA[2][0], prOwnA[3][0]};
                float o1[4] = {prOwnA[0][1], prOwnA[1][1], prOwnA[2][1], prOwnA[3][1]};
                finalize_half(OFF_HA, 0, t, o0, o1, xqA, xvA);
            }
        }
        {
            float prBt[4][3];
            gemm_body<3>(kh, WcD, wr, gb, (const ulonglong2*)(sm + OFF_HB), j, prBt);
            exportB(prBt, prOwnBv);
        }
        __syncthreads();
    }
    // drain: finalize_B(511)
    if (kh < 2) {
        float o0[4] = {prOwnBv[0][0], prOwnBv[1][0], prOwnBv[2][0], prOwnBv[3][0]};
        float o1[4] = {prOwnBv[0][1], prOwnBv[1][1], prOwnBv[2][1], prOwnBv[3][1]};
        finalize_half(OFF_HB, 1, S_LEN - 1, o0, o1, xqB, xvB);
    }
    __syncthreads();

    if (PHASE == 2 && tid < 224) {
        int w = tid >> 5, lane = tid & 31;
        if (w < valid) {
            const float* hrow = sm + (w < 4 ? OFF_HA + w * HID : OFF_HB + (w - 4) * HID);
            float s = 0.f;
#pragma unroll
            for (int m = 0; m < HID; m += 32)
                s += hrow[lane + m] * __ldg(fcw + lane + m);
#pragma unroll
            for (int o = 16; o > 0; o >>= 1) s += __shfl_down_sync(0xffffffffu, s, o);
            if (lane == 0) out[bg0 + w] = s + __ldg(fcb);
        }
    }
}

// ---------------- launch ----------------
extern "C" void kernel_launch(void* const* d_in, const int* in_sizes, int n_in,
                              void* d_out, int out_size) {
    const float* x    = (const float*)d_in[0];
    const float* wih0 = (const float*)d_in[1];
    const float* whh0 = (const float*)d_in[2];
    const float* bih0 = (const float*)d_in[3];
    const float* bhh0 = (const float*)d_in[4];
    const float* wih1 = (const float*)d_in[5];
    const float* whh1 = (const float*)d_in[6];
    const float* bih1 = (const float*)d_in[7];
    const float* bhh1 = (const float*)d_in[8];
    const float* fcw  = (const float*)d_in[9];
    const float* fcb  = (const float*)d_in[10];
    float* out = (float*)d_out;
    (void)in_sizes; (void)n_in; (void)out_size;

    cudaFuncSetAttribute(lstm_phase<1>, cudaFuncAttributeMaxDynamicSharedMemorySize, PH_SMEM_BYTES);
    cudaFuncSetAttribute(lstm_phase<2>, cudaFuncAttributeMaxDynamicSharedMemorySize, PH_SMEM_BYTES);
    cudaFuncSetAttribute(xg1_gemm,      cudaFuncAttributeMaxDynamicSharedMemorySize, GM_SMEM_BYTES);

    pack_kernel<<<(GATES * HID + 255) / 256, 256>>>(whh0, whh1, wih1);
    lstm_phase<1><<<NBLK, NTH, PH_SMEM_BYTES>>>(x, wih0, bih0, bhh0, fcw, fcb, out);
    xg1_gemm<<<dim3(2, NBLK, 4), GM_THREADS, GM_SMEM_BYTES>>>(bih1, bhh1);
    lstm_phase<2><<<NBLK, NTH, PH_SMEM_BYTES>>>(x, wih0, bih1, bhh1, fcw, fcb, out);
}